// round 9
// baseline (speedup 1.0000x reference)
#include <cuda_runtime.h>
#include <cuda_fp16.h>
#include <cstdint>
#include <cstddef>

// ---------------- Problem constants ----------------
#define NNODES 200000
#define NEDGES 400000
#define NGRAPHS 4096
#define HDIM 300
#define H2DIM 600
#define NLAYERS 5

// ---------------- Scratch (device globals; no allocation allowed) ----------------
__device__ float g_h[(size_t)NNODES * HDIM];     // node features
__device__ float g_agg[(size_t)NNODES * HDIM];   // scatter-add accumulator
__device__ float g_t[(size_t)NNODES * H2DIM];    // hidden 2H activations
__device__ float g_gsum[(size_t)NGRAPHS * HDIM]; // pooled sums
__device__ float g_gcnt[NGRAPHS];                // pooled counts

// ---------------- PTX helpers ----------------
__device__ __forceinline__ void red_add_v4(float* p, float4 v) {
    asm volatile("red.global.add.v4.f32 [%0], {%1, %2, %3, %4};"
                 :: "l"(p), "f"(v.x), "f"(v.y), "f"(v.z), "f"(v.w) : "memory");
}

// fp16 tensor-core mma: D(16x8) += A(16x16) * B(16x8), fp32 accum.
__device__ __forceinline__ void mma_f16(float* d, const unsigned* a, const unsigned* b) {
    asm volatile(
        "mma.sync.aligned.m16n8k16.row.col.f32.f16.f16.f32 "
        "{%0,%1,%2,%3}, {%4,%5,%6,%7}, {%8,%9}, {%0,%1,%2,%3};"
        : "+f"(d[0]), "+f"(d[1]), "+f"(d[2]), "+f"(d[3])
        : "r"(a[0]), "r"(a[1]), "r"(a[2]), "r"(a[3]), "r"(b[0]), "r"(b[1]));
}

// 2-way fp16 split: v = h0 + h1 + O(2^-22 v)
__device__ __forceinline__ void split2(float v, __half& h0, __half& h1) {
    h0 = __float2half_rn(v);
    h1 = __float2half_rn(v - __half2float(h0));
}
__device__ __forceinline__ unsigned pack_h(__half a, __half b) {
    __half2 t = __halves2half2(a, b);
    return *reinterpret_cast<unsigned*>(&t);
}

// ---------------- Zeroing kernels ----------------
__global__ void zero_agg_kernel() {
    float4* p = reinterpret_cast<float4*>(g_agg);
    int n4 = (NNODES * HDIM) / 4;
    for (int i = blockIdx.x * blockDim.x + threadIdx.x; i < n4; i += gridDim.x * blockDim.x)
        p[i] = make_float4(0.f, 0.f, 0.f, 0.f);
}
__global__ void zero_pool_kernel() {
    float4* p = reinterpret_cast<float4*>(g_gsum);
    int n4 = (NGRAPHS * HDIM) / 4;
    for (int i = blockIdx.x * blockDim.x + threadIdx.x; i < n4; i += gridDim.x * blockDim.x)
        p[i] = make_float4(0.f, 0.f, 0.f, 0.f);
    for (int i = blockIdx.x * blockDim.x + threadIdx.x; i < NGRAPHS; i += gridDim.x * blockDim.x)
        g_gcnt[i] = 0.f;
}

// ---------------- Atom encoder ----------------
__global__ void atom_kernel(const int* __restrict__ x, const float* __restrict__ atom_emb) {
    int n = blockIdx.x;
    __shared__ int sx[9];
    if (threadIdx.x < 9) sx[threadIdx.x] = x[n * 9 + threadIdx.x];
    __syncthreads();
    for (int j = threadIdx.x; j < HDIM; j += blockDim.x) {
        float s = 0.f;
#pragma unroll
        for (int f = 0; f < 9; f++)
            s += __ldg(&atom_emb[((size_t)(f * 120 + sx[f])) * HDIM + j]);
        g_h[(size_t)n * HDIM + j] = s;
    }
}

// ---------------- Edge kernel: agg[dst] += relu(h[src] + e) ----------------
__global__ void edge_kernel(const int* __restrict__ edge_index,
                            const int* __restrict__ edge_attr,
                            const float* __restrict__ bond_l) {
    int e = blockIdx.x * 8 + (threadIdx.x >> 5);
    if (e >= NEDGES) return;
    int lane = threadIdx.x & 31;
    int src = __ldg(&edge_index[e]);
    int dst = __ldg(&edge_index[NEDGES + e]);
    int a0 = __ldg(&edge_attr[e * 3 + 0]);
    int a1 = __ldg(&edge_attr[e * 3 + 1]);
    int a2 = __ldg(&edge_attr[e * 3 + 2]);
    const float4* b0 = reinterpret_cast<const float4*>(bond_l + (size_t)(0 * 16 + a0) * HDIM);
    const float4* b1 = reinterpret_cast<const float4*>(bond_l + (size_t)(1 * 16 + a1) * HDIM);
    const float4* b2 = reinterpret_cast<const float4*>(bond_l + (size_t)(2 * 16 + a2) * HDIM);
    const float4* hs = reinterpret_cast<const float4*>(g_h + (size_t)src * HDIM);
    float* ag = g_agg + (size_t)dst * HDIM;
#pragma unroll 3
    for (int c = lane; c < HDIM / 4; c += 32) {
        float4 e0 = __ldg(&b0[c]);
        float4 e1 = __ldg(&b1[c]);
        float4 e2 = __ldg(&b2[c]);
        float4 hv = hs[c];
        float4 m;
        m.x = fmaxf(hv.x + e0.x + e1.x + e2.x, 0.f);
        m.y = fmaxf(hv.y + e0.y + e1.y + e2.y, 0.f);
        m.z = fmaxf(hv.z + e0.z + e1.z + e2.z, 0.f);
        m.w = fmaxf(hv.w + e0.w + e1.w + e2.w, 0.f);
        red_add_v4(ag + 4 * c, m);
    }
}

// ---------------- Tensor-core GEMM (3xFP16 split, mma.sync m16n8k16) ----------------
// Block tile 128x128, 8 warps, each warp 64x32 (4x4 m16n8k16 tiles per K16-chunk).
// A = A0 + A1 (fp16 split), B = B0 + B1. acc += A0*B0 + A0*B1 + A1*B0 (A1*B1 dropped).
// Splits computed ONCE at smem-store time; tiles stored as packed half2 words,
// stride 12 words/row (conflict-free for the fragment access pattern).
// MODE 1: A=(1+eps)*g_h+g_agg [K=300], B=W1[300,600], epilogue BN+ReLU -> g_t
// MODE 2: A=g_t [K=600],          B=W2[600,300], epilogue +b2     -> g_h
#define GBM 128
#define GBN 128
#define GKC 16

template <int MODE>
__global__ __launch_bounds__(256) void gemm_mma_kernel(
    const float* __restrict__ Bmat,
    const float* __restrict__ bias,
    const float* __restrict__ gml, const float* __restrict__ btl,
    const float* __restrict__ mnl, const float* __restrict__ vrl,
    const float* __restrict__ epsp) {
    constexpr int K = (MODE == 1) ? HDIM : H2DIM;
    constexpr int NC = (MODE == 1) ? H2DIM : HDIM;
    constexpr int NKT = (K + GKC - 1) / GKC;

    // [row/col][k-pair word]; 8 words used, stride 12 for conflict-free LDS
    __shared__ unsigned A0s[GBM][12], A1s[GBM][12];
    __shared__ unsigned B0s[GBN][12], B1s[GBN][12];

    int tid = threadIdx.x;
    int w = tid >> 5, lane = tid & 31;
    int wm = w & 1, wn = w >> 1;
    int gid = lane >> 2, tig = lane & 3;
    int rowBase = blockIdx.y * GBM, colBase = blockIdx.x * GBN;

    float epv = 0.f;
    if (MODE == 1) epv = 1.0f + __ldg(epsp);

    float acc[4][4][4];
#pragma unroll
    for (int mt = 0; mt < 4; mt++)
#pragma unroll
        for (int nt = 0; nt < 4; nt++)
#pragma unroll
            for (int i = 0; i < 4; i++) acc[mt][nt][i] = 0.f;

    auto loadA = [&](int kt, float4* r) {
#pragma unroll
        for (int i = 0; i < 2; i++) {
            int id = tid * 2 + i;
            int row = id >> 2, q = id & 3;
            int gr = rowBase + row;
            int gk = kt * GKC + q * 4;
            float4 v = make_float4(0.f, 0.f, 0.f, 0.f);
            if (gk < K && gr < NNODES) {
                if (MODE == 1) {
                    float4 hv = *reinterpret_cast<const float4*>(g_h + (size_t)gr * HDIM + gk);
                    float4 gv = *reinterpret_cast<const float4*>(g_agg + (size_t)gr * HDIM + gk);
                    v.x = fmaf(epv, hv.x, gv.x);
                    v.y = fmaf(epv, hv.y, gv.y);
                    v.z = fmaf(epv, hv.z, gv.z);
                    v.w = fmaf(epv, hv.w, gv.w);
                } else {
                    v = *reinterpret_cast<const float4*>(g_t + (size_t)gr * H2DIM + gk);
                }
            }
            r[i] = v;
        }
    };
    auto loadB = [&](int kt, float4* r) {
#pragma unroll
        for (int i = 0; i < 2; i++) {
            int id = tid * 2 + i;
            int k = id >> 5, n4 = id & 31;
            int gk = kt * GKC + k;
            int gc = colBase + n4 * 4;
            float4 v = make_float4(0.f, 0.f, 0.f, 0.f);
            if (gk < K && gc < NC)
                v = *reinterpret_cast<const float4*>(Bmat + (size_t)gk * NC + gc);
            r[i] = v;
        }
    };

    float4 aCur[2], bCur[2], aNxt[2], bNxt[2];
    loadA(0, aCur);
    loadB(0, bCur);

    for (int kt = 0; kt < NKT; kt++) {
        __syncthreads();
        // Store A tiles with fp16 split (row-major k-pairs)
#pragma unroll
        for (int i = 0; i < 2; i++) {
            int id = tid * 2 + i;
            int row = id >> 2, q = id & 3;
            float4 v = aCur[i];
            __half h0x, h1x, h0y, h1y, h0z, h1z, h0w, h1w;
            split2(v.x, h0x, h1x);
            split2(v.y, h0y, h1y);
            split2(v.z, h0z, h1z);
            split2(v.w, h0w, h1w);
            A0s[row][q * 2] = pack_h(h0x, h0y);
            A0s[row][q * 2 + 1] = pack_h(h0z, h0w);
            A1s[row][q * 2] = pack_h(h1x, h1y);
            A1s[row][q * 2 + 1] = pack_h(h1z, h1w);
        }
        // Store B tiles with fp16 split (col-major: [col][k-pair], 2B stores)
#pragma unroll
        for (int i = 0; i < 2; i++) {
            int id = tid * 2 + i;
            int k = id >> 5, n4 = id & 31;
            float4 v = bCur[i];
            float vv[4] = {v.x, v.y, v.z, v.w};
#pragma unroll
            for (int j = 0; j < 4; j++) {
                int col = n4 * 4 + j;
                __half h0, h1;
                split2(vv[j], h0, h1);
                reinterpret_cast<__half*>(&B0s[col][0])[k] = h0;
                reinterpret_cast<__half*>(&B1s[col][0])[k] = h1;
            }
        }
        __syncthreads();

        bool more = (kt + 1 < NKT);
        if (more) {
            loadA(kt + 1, aNxt);
            loadB(kt + 1, bNxt);
        }

        // Fragments: A (both splits), then per-nt B and 3 MMA terms
        unsigned a0f[4][4], a1f[4][4];
#pragma unroll
        for (int mt = 0; mt < 4; mt++) {
            int r0 = wm * 64 + mt * 16 + gid;
            a0f[mt][0] = A0s[r0][tig];
            a0f[mt][1] = A0s[r0 + 8][tig];
            a0f[mt][2] = A0s[r0][tig + 4];
            a0f[mt][3] = A0s[r0 + 8][tig + 4];
            a1f[mt][0] = A1s[r0][tig];
            a1f[mt][1] = A1s[r0 + 8][tig];
            a1f[mt][2] = A1s[r0][tig + 4];
            a1f[mt][3] = A1s[r0 + 8][tig + 4];
        }
#pragma unroll
        for (int nt = 0; nt < 4; nt++) {
            int c = wn * 32 + nt * 8 + gid;
            unsigned b0[2], b1[2];
            b0[0] = B0s[c][tig];
            b0[1] = B0s[c][tig + 4];
            b1[0] = B1s[c][tig];
            b1[1] = B1s[c][tig + 4];
#pragma unroll
            for (int mt = 0; mt < 4; mt++) {
                mma_f16(acc[mt][nt], a0f[mt], b0);
                mma_f16(acc[mt][nt], a0f[mt], b1);
                mma_f16(acc[mt][nt], a1f[mt], b0);
            }
        }

        if (more) {
#pragma unroll
            for (int i = 0; i < 2; i++) { aCur[i] = aNxt[i]; bCur[i] = bNxt[i]; }
        }
    }

    // Epilogue (C layout of m16n8k16 == m16n8k8)
#pragma unroll
    for (int nt = 0; nt < 4; nt++) {
        int c = colBase + wn * 32 + nt * 8 + 2 * tig;
        if (c >= NC) continue;  // pairs (c, c+1) never straddle NC (NC even, c even)
        float s0, s1, t0, t1;
        if (MODE == 1) {
            s0 = __ldg(&gml[c]) * rsqrtf(__ldg(&vrl[c]) + 1e-5f);
            t0 = (__ldg(&bias[c]) - __ldg(&mnl[c])) * s0 + __ldg(&btl[c]);
            s1 = __ldg(&gml[c + 1]) * rsqrtf(__ldg(&vrl[c + 1]) + 1e-5f);
            t1 = (__ldg(&bias[c + 1]) - __ldg(&mnl[c + 1])) * s1 + __ldg(&btl[c + 1]);
        } else {
            s0 = s1 = 1.f;
            t0 = __ldg(&bias[c]);
            t1 = __ldg(&bias[c + 1]);
        }
#pragma unroll
        for (int mt = 0; mt < 4; mt++) {
            int r0 = rowBase + wm * 64 + mt * 16 + gid;
            int r1 = r0 + 8;
            if (r0 < NNODES) {
                float v0 = fmaf(acc[mt][nt][0], s0, t0);
                float v1 = fmaf(acc[mt][nt][1], s1, t1);
                float2 o;
                if (MODE == 1) {
                    o.x = fmaxf(v0, 0.f);
                    o.y = fmaxf(v1, 0.f);
                    *reinterpret_cast<float2*>(g_t + (size_t)r0 * H2DIM + c) = o;
                } else {
                    o.x = v0;
                    o.y = v1;
                    *reinterpret_cast<float2*>(g_h + (size_t)r0 * HDIM + c) = o;
                }
            }
            if (r1 < NNODES) {
                float v0 = fmaf(acc[mt][nt][2], s0, t0);
                float v1 = fmaf(acc[mt][nt][3], s1, t1);
                float2 o;
                if (MODE == 1) {
                    o.x = fmaxf(v0, 0.f);
                    o.y = fmaxf(v1, 0.f);
                    *reinterpret_cast<float2*>(g_t + (size_t)r1 * H2DIM + c) = o;
                } else {
                    o.x = v0;
                    o.y = v1;
                    *reinterpret_cast<float2*>(g_h + (size_t)r1 * HDIM + c) = o;
                }
            }
        }
    }
}

// ---------------- Pooling scatter ----------------
__global__ void pool_kernel(const int* __restrict__ batch) {
    int n = blockIdx.x * 8 + (threadIdx.x >> 5);
    if (n >= NNODES) return;
    int lane = threadIdx.x & 31;
    int g = __ldg(&batch[n]);
    const float4* hr = reinterpret_cast<const float4*>(g_h + (size_t)n * HDIM);
    float* gs = g_gsum + (size_t)g * HDIM;
#pragma unroll 3
    for (int c = lane; c < HDIM / 4; c += 32)
        red_add_v4(gs + 4 * c, hr[c]);
    if (lane == 0) atomicAdd(&g_gcnt[g], 1.0f);
}

// ---------------- Final: graph_feature + logits ----------------
__global__ void final_kernel(const float* __restrict__ cls_W, const float* __restrict__ cls_b,
                             float* __restrict__ out, int write_gf) {
    int g = blockIdx.x;
    int tid = threadIdx.x;
    float inv = 1.0f / fmaxf(g_gcnt[g], 1.0f);
    float d0 = 0.f, d1 = 0.f;
    for (int j = tid; j < HDIM; j += blockDim.x) {
        float gf = g_gsum[(size_t)g * HDIM + j] * inv;
        if (write_gf) out[2 * NGRAPHS + (size_t)g * HDIM + j] = gf;
        d0 += gf * __ldg(&cls_W[j * 2 + 0]);
        d1 += gf * __ldg(&cls_W[j * 2 + 1]);
    }
    __shared__ float s0[128], s1[128];
    s0[tid] = d0;
    s1[tid] = d1;
    __syncthreads();
    for (int o = 64; o > 0; o >>= 1) {
        if (tid < o) { s0[tid] += s0[tid + o]; s1[tid] += s1[tid + o]; }
        __syncthreads();
    }
    if (tid == 0) {
        out[g * 2 + 0] = s0[0] + __ldg(&cls_b[0]);
        out[g * 2 + 1] = s1[0] + __ldg(&cls_b[1]);
    }
}

// ---------------- Launcher ----------------
extern "C" void kernel_launch(void* const* d_in, const int* in_sizes, int n_in,
                              void* d_out, int out_size) {
    const int* x          = (const int*)d_in[0];
    const int* edge_index = (const int*)d_in[1];
    const int* edge_attr  = (const int*)d_in[2];
    const int* batch      = (const int*)d_in[3];
    const float* atom_emb = (const float*)d_in[4];
    const float* bond_emb = (const float*)d_in[5];
    const float* eps      = (const float*)d_in[6];
    const float* W1       = (const float*)d_in[7];
    const float* b1       = (const float*)d_in[8];
    const float* bn_gamma = (const float*)d_in[9];
    const float* bn_beta  = (const float*)d_in[10];
    const float* bn_mean  = (const float*)d_in[11];
    const float* bn_var   = (const float*)d_in[12];
    const float* W2       = (const float*)d_in[13];
    const float* b2       = (const float*)d_in[14];
    const float* cls_W    = (const float*)d_in[15];
    const float* cls_b    = (const float*)d_in[16];
    float* out = (float*)d_out;

    atom_kernel<<<NNODES, 128>>>(x, atom_emb);
    zero_pool_kernel<<<1184, 256>>>();

    dim3 g1grid((H2DIM + GBN - 1) / GBN, (NNODES + GBM - 1) / GBM); // 5 x 1563
    dim3 g2grid((HDIM + GBN - 1) / GBN, (NNODES + GBM - 1) / GBM);  // 3 x 1563

    for (int l = 0; l < NLAYERS; l++) {
        zero_agg_kernel<<<4096, 256>>>();
        edge_kernel<<<(NEDGES + 7) / 8, 256>>>(edge_index, edge_attr,
                                               bond_emb + (size_t)l * 3 * 16 * HDIM);
        gemm_mma_kernel<1><<<g1grid, 256>>>(W1 + (size_t)l * HDIM * H2DIM,
                                            b1 + (size_t)l * H2DIM,
                                            bn_gamma + (size_t)l * H2DIM,
                                            bn_beta + (size_t)l * H2DIM,
                                            bn_mean + (size_t)l * H2DIM,
                                            bn_var + (size_t)l * H2DIM,
                                            eps + l);
        gemm_mma_kernel<2><<<g2grid, 256>>>(W2 + (size_t)l * H2DIM * HDIM,
                                            b2 + (size_t)l * HDIM,
                                            nullptr, nullptr, nullptr, nullptr, nullptr);
    }

    pool_kernel<<<(NNODES + 7) / 8, 256>>>(batch);
    int write_gf = (out_size >= 2 * NGRAPHS + NGRAPHS * HDIM) ? 1 : 0;
    final_kernel<<<NGRAPHS, 128>>>(cls_W, cls_b, out, write_gf);
}

// round 13
// speedup vs baseline: 1.5438x; 1.5438x over previous
#include <cuda_runtime.h>
#include <cuda_fp16.h>
#include <cstdint>
#include <cstddef>

// ---------------- Problem constants ----------------
#define NNODES 200000
#define NEDGES 400000
#define NGRAPHS 4096
#define HDIM 300
#define H2DIM 600
#define NLAYERS 5
#define KP1 320   // padded K for gemm1 operands (>=300, mult of 32)
#define KP2 608   // padded K for gemm2 operands (>=600, mult of 32)

// ---------------- Scratch (device globals; no allocation allowed) ----------------
__device__ float g_h[(size_t)NNODES * HDIM];      // node features (fp32)
__device__ float g_agg[(size_t)NNODES * HDIM];    // scatter-add accumulator
__device__ __half g_a0[(size_t)NNODES * KP1];     // gemm1 A hi-split
__device__ __half g_a1[(size_t)NNODES * KP1];     // gemm1 A lo-split
__device__ __half g_t0[(size_t)NNODES * KP2];     // gemm1 out / gemm2 A hi-split
__device__ __half g_t1[(size_t)NNODES * KP2];     // lo-split
__device__ __half g_w1p0[(size_t)NLAYERS * H2DIM * KP1];  // W1 transposed+split [l][n][k]
__device__ __half g_w1p1[(size_t)NLAYERS * H2DIM * KP1];
__device__ __half g_w2p0[(size_t)NLAYERS * HDIM * KP2];   // W2 transposed+split
__device__ __half g_w2p1[(size_t)NLAYERS * HDIM * KP2];
__device__ float g_gsum[(size_t)NGRAPHS * HDIM];
__device__ float g_gcnt[NGRAPHS];

// ---------------- PTX helpers ----------------
__device__ __forceinline__ void red_add_v4(float* p, float4 v) {
    asm volatile("red.global.add.v4.f32 [%0], {%1, %2, %3, %4};"
                 :: "l"(p), "f"(v.x), "f"(v.y), "f"(v.z), "f"(v.w) : "memory");
}
__device__ __forceinline__ uint32_t smem_u32(const void* p) {
    uint32_t a;
    asm("{ .reg .u64 t; cvta.to.shared.u64 t, %1; cvt.u32.u64 %0, t; }" : "=r"(a) : "l"(p));
    return a;
}
__device__ __forceinline__ void mma_f16(float* d, const unsigned* a, const unsigned* b) {
    asm volatile(
        "mma.sync.aligned.m16n8k16.row.col.f32.f16.f16.f32 "
        "{%0,%1,%2,%3}, {%4,%5,%6,%7}, {%8,%9}, {%0,%1,%2,%3};"
        : "+f"(d[0]), "+f"(d[1]), "+f"(d[2]), "+f"(d[3])
        : "r"(a[0]), "r"(a[1]), "r"(a[2]), "r"(a[3]), "r"(b[0]), "r"(b[1]));
}
__device__ __forceinline__ void ldm_x4(unsigned* r, uint32_t addr) {
    asm volatile("ldmatrix.sync.aligned.m8n8.x4.shared.b16 {%0,%1,%2,%3}, [%4];"
                 : "=r"(r[0]), "=r"(r[1]), "=r"(r[2]), "=r"(r[3]) : "r"(addr));
}
__device__ __forceinline__ void split2(float v, __half& h0, __half& h1) {
    h0 = __float2half_rn(v);
    h1 = __float2half_rn(v - __half2float(h0));
}

// ---------------- Zeroing kernels ----------------
__global__ void zero_agg_kernel() {
    float4* p = reinterpret_cast<float4*>(g_agg);
    int n4 = (NNODES * HDIM) / 4;
    for (int i = blockIdx.x * blockDim.x + threadIdx.x; i < n4; i += gridDim.x * blockDim.x)
        p[i] = make_float4(0.f, 0.f, 0.f, 0.f);
}
__global__ void zero_pool_kernel() {
    float4* p = reinterpret_cast<float4*>(g_gsum);
    int n4 = (NGRAPHS * HDIM) / 4;
    for (int i = blockIdx.x * blockDim.x + threadIdx.x; i < n4; i += gridDim.x * blockDim.x)
        p[i] = make_float4(0.f, 0.f, 0.f, 0.f);
    for (int i = blockIdx.x * blockDim.x + threadIdx.x; i < NGRAPHS; i += gridDim.x * blockDim.x)
        g_gcnt[i] = 0.f;
}

// ---------------- Weight prepack: transpose + fp16 split, all layers ----------------
// Range A: W1 [L][300][600] -> g_w1p* [L][600][KP1]
// Range B: W2 [L][600][300] -> g_w2p* [L][300][KP2]
#define W1P_TOTAL (NLAYERS * H2DIM * KP1)
#define W2P_TOTAL (NLAYERS * HDIM * KP2)
__global__ void prepack_w_kernel(const float* __restrict__ W1, const float* __restrict__ W2) {
    int idx = blockIdx.x * blockDim.x + threadIdx.x;
    if (idx < W1P_TOTAL) {
        int l = idx / (H2DIM * KP1);
        int rem = idx % (H2DIM * KP1);
        int n = rem / KP1, k = rem % KP1;
        float v = (k < HDIM) ? __ldg(&W1[((size_t)l * HDIM + k) * H2DIM + n]) : 0.f;
        __half h0, h1;
        split2(v, h0, h1);
        g_w1p0[idx] = h0;
        g_w1p1[idx] = h1;
    } else if (idx < W1P_TOTAL + W2P_TOTAL) {
        int j = idx - W1P_TOTAL;
        int l = j / (HDIM * KP2);
        int rem = j % (HDIM * KP2);
        int n = rem / KP2, k = rem % KP2;
        float v = (k < H2DIM) ? __ldg(&W2[((size_t)l * H2DIM + k) * HDIM + n]) : 0.f;
        __half h0, h1;
        split2(v, h0, h1);
        g_w2p0[j] = h0;
        g_w2p1[j] = h1;
    }
}

// ---------------- A prepack for gemm1: v=(1+eps)h+agg, split -> g_a0/g_a1 ----------------
__global__ void prepack_a_kernel(const float* __restrict__ epsp) {
    int idx = blockIdx.x * blockDim.x + threadIdx.x;  // row * 80 + g4
    if (idx >= NNODES * 80) return;
    int row = idx / 80, g4 = idx % 80;
    __half2 z0[2], z1[2];
    if (g4 < 75) {
        float epv = 1.0f + __ldg(epsp);
        float4 hv = *reinterpret_cast<const float4*>(g_h + (size_t)row * HDIM + g4 * 4);
        float4 gv = *reinterpret_cast<const float4*>(g_agg + (size_t)row * HDIM + g4 * 4);
        float v[4] = {fmaf(epv, hv.x, gv.x), fmaf(epv, hv.y, gv.y),
                      fmaf(epv, hv.z, gv.z), fmaf(epv, hv.w, gv.w)};
        __half h0[4], h1[4];
#pragma unroll
        for (int j = 0; j < 4; j++) split2(v[j], h0[j], h1[j]);
        z0[0] = __halves2half2(h0[0], h0[1]);
        z0[1] = __halves2half2(h0[2], h0[3]);
        z1[0] = __halves2half2(h1[0], h1[1]);
        z1[1] = __halves2half2(h1[2], h1[3]);
    } else {
        z0[0] = z0[1] = z1[0] = z1[1] = __halves2half2(__ushort_as_half(0), __ushort_as_half(0));
    }
    *reinterpret_cast<__half2*>(g_a0 + (size_t)row * KP1 + g4 * 4) = z0[0];
    *reinterpret_cast<__half2*>(g_a0 + (size_t)row * KP1 + g4 * 4 + 2) = z0[1];
    *reinterpret_cast<__half2*>(g_a1 + (size_t)row * KP1 + g4 * 4) = z1[0];
    *reinterpret_cast<__half2*>(g_a1 + (size_t)row * KP1 + g4 * 4 + 2) = z1[1];
}

// ---------------- Atom encoder ----------------
__global__ void atom_kernel(const int* __restrict__ x, const float* __restrict__ atom_emb) {
    int n = blockIdx.x;
    __shared__ int sx[9];
    if (threadIdx.x < 9) sx[threadIdx.x] = x[n * 9 + threadIdx.x];
    __syncthreads();
    for (int j = threadIdx.x; j < HDIM; j += blockDim.x) {
        float s = 0.f;
#pragma unroll
        for (int f = 0; f < 9; f++)
            s += __ldg(&atom_emb[((size_t)(f * 120 + sx[f])) * HDIM + j]);
        g_h[(size_t)n * HDIM + j] = s;
    }
}

// ---------------- Edge kernel: agg[dst] += relu(h[src] + e) ----------------
__global__ void edge_kernel(const int* __restrict__ edge_index,
                            const int* __restrict__ edge_attr,
                            const float* __restrict__ bond_l) {
    int e = blockIdx.x * 8 + (threadIdx.x >> 5);
    if (e >= NEDGES) return;
    int lane = threadIdx.x & 31;
    int src = __ldg(&edge_index[e]);
    int dst = __ldg(&edge_index[NEDGES + e]);
    int a0 = __ldg(&edge_attr[e * 3 + 0]);
    int a1 = __ldg(&edge_attr[e * 3 + 1]);
    int a2 = __ldg(&edge_attr[e * 3 + 2]);
    const float4* b0 = reinterpret_cast<const float4*>(bond_l + (size_t)(0 * 16 + a0) * HDIM);
    const float4* b1 = reinterpret_cast<const float4*>(bond_l + (size_t)(1 * 16 + a1) * HDIM);
    const float4* b2 = reinterpret_cast<const float4*>(bond_l + (size_t)(2 * 16 + a2) * HDIM);
    const float4* hs = reinterpret_cast<const float4*>(g_h + (size_t)src * HDIM);
    float* ag = g_agg + (size_t)dst * HDIM;
#pragma unroll 3
    for (int c = lane; c < HDIM / 4; c += 32) {
        float4 e0 = __ldg(&b0[c]);
        float4 e1 = __ldg(&b1[c]);
        float4 e2 = __ldg(&b2[c]);
        float4 hv = hs[c];
        float4 m;
        m.x = fmaxf(hv.x + e0.x + e1.x + e2.x, 0.f);
        m.y = fmaxf(hv.y + e0.y + e1.y + e2.y, 0.f);
        m.z = fmaxf(hv.z + e0.z + e1.z + e2.z, 0.f);
        m.w = fmaxf(hv.w + e0.w + e1.w + e2.w, 0.f);
        red_add_v4(ag + 4 * c, m);
    }
}

// ---------------- Tensor-core GEMM (prepacked 3xFP16 split, ldmatrix + mma) ----------------
// 512 threads (16 warps, 4x4), block tile 128x128, warp tile 32x32, K-chunk 32.
// smem: double-buffered stages of 4 tiles (Ah, Al, Bh, Bl), each 128x32 half (8KB),
// XOR-swizzled 16B chunks: slot = w4 ^ ((row>>1)&3) -> conflict-free STS + ldmatrix.
// acc += Ah*Bh + Ah*Bl + Al*Bh.
// MODE 1: A=g_a* [KP1], B=W1p, epilogue BN+ReLU -> split -> g_t*
// MODE 2: A=g_t* [KP2], B=W2p, epilogue +b2 -> g_h
#define TILE_B 8192
#define STAGE_B (4 * TILE_B)
#define GSMEM (2 * STAGE_B)

template <int MODE>
__global__ __launch_bounds__(512) void gemm_f16_kernel(
    int l,
    const float* __restrict__ bias,
    const float* __restrict__ gml, const float* __restrict__ btl,
    const float* __restrict__ mnl, const float* __restrict__ vrl) {
    constexpr int KP = (MODE == 1) ? KP1 : KP2;
    constexpr int NC = (MODE == 1) ? H2DIM : HDIM;
    constexpr int NKT = KP / 32;

    extern __shared__ __align__(128) char smem[];
    const uint32_t sb = smem_u32(smem);

    const __half* Ah = (MODE == 1) ? g_a0 : g_t0;
    const __half* Al = (MODE == 1) ? g_a1 : g_t1;
    const __half* Bh = (MODE == 1) ? (g_w1p0 + (size_t)l * H2DIM * KP1)
                                   : (g_w2p0 + (size_t)l * HDIM * KP2);
    const __half* Bl = (MODE == 1) ? (g_w1p1 + (size_t)l * H2DIM * KP1)
                                   : (g_w2p1 + (size_t)l * HDIM * KP2);

    int tid = threadIdx.x;
    int lane = tid & 31, w = tid >> 5;
    int wr = w & 3, wc = w >> 2;
    int gid = lane >> 2, tig = lane & 3;
    int ml = lane & 15, khalf = lane >> 4;
    int rowBase = blockIdx.y * 128, colBase = blockIdx.x * 128;

    // LDG/STS mapping: thread -> (lrow, w4)
    int lrow = tid >> 2, w4 = tid & 3;
    int garow = rowBase + lrow;
    int gbrow = colBase + lrow;
    bool aok = (garow < NNODES);
    bool bok = (gbrow < NC);
    const uint4* pAh = reinterpret_cast<const uint4*>(Ah + (size_t)garow * KP + w4 * 8);
    const uint4* pAl = reinterpret_cast<const uint4*>(Al + (size_t)garow * KP + w4 * 8);
    const uint4* pBh = reinterpret_cast<const uint4*>(Bh + (size_t)gbrow * KP + w4 * 8);
    const uint4* pBl = reinterpret_cast<const uint4*>(Bl + (size_t)gbrow * KP + w4 * 8);
    const uint4 zz = make_uint4(0, 0, 0, 0);
    // each kt advances 32 halves = 4 uint4
    uint32_t sts_off = (uint32_t)lrow * 64 + (uint32_t)((w4 ^ ((lrow >> 1) & 3)) * 16);

    float acc[2][4][4];
#pragma unroll
    for (int mt = 0; mt < 2; mt++)
#pragma unroll
        for (int nt = 0; nt < 4; nt++)
#pragma unroll
            for (int i = 0; i < 4; i++) acc[mt][nt][i] = 0.f;

    uint4 vah, val, vbh, vbl;
    vah = aok ? pAh[0] : zz;
    val = aok ? pAl[0] : zz;
    vbh = bok ? pBh[0] : zz;
    vbl = bok ? pBl[0] : zz;
    {
        char* st = smem;  // stage 0
        *reinterpret_cast<uint4*>(st + 0 * TILE_B + sts_off) = vah;
        *reinterpret_cast<uint4*>(st + 1 * TILE_B + sts_off) = val;
        *reinterpret_cast<uint4*>(st + 2 * TILE_B + sts_off) = vbh;
        *reinterpret_cast<uint4*>(st + 3 * TILE_B + sts_off) = vbl;
    }
    __syncthreads();

    for (int kt = 0; kt < NKT; kt++) {
        bool more = (kt + 1 < NKT);
        if (more) {
            int o = (kt + 1) * 4;
            vah = aok ? pAh[o] : zz;
            val = aok ? pAl[o] : zz;
            vbh = bok ? pBh[o] : zz;
            vbl = bok ? pBl[o] : zz;
        }

        uint32_t stg = sb + (uint32_t)(kt & 1) * STAGE_B;
#pragma unroll
        for (int kc = 0; kc < 2; kc++) {
            unsigned ahf[2][4], alf[2][4], bhf[2][4], blf[2][4];
#pragma unroll
            for (int mt = 0; mt < 2; mt++) {
                int r = wr * 32 + mt * 16 + ml;
                uint32_t off = (uint32_t)r * 64 +
                               (uint32_t)(((kc * 2 + khalf) ^ ((r >> 1) & 3)) * 16);
                ldm_x4(ahf[mt], stg + 0 * TILE_B + off);
                ldm_x4(alf[mt], stg + 1 * TILE_B + off);
            }
#pragma unroll
            for (int ng = 0; ng < 2; ng++) {
                int r = wc * 32 + ng * 16 + ml;
                uint32_t off = (uint32_t)r * 64 +
                               (uint32_t)(((kc * 2 + khalf) ^ ((r >> 1) & 3)) * 16);
                ldm_x4(bhf[ng], stg + 2 * TILE_B + off);
                ldm_x4(blf[ng], stg + 3 * TILE_B + off);
            }
#pragma unroll
            for (int mt = 0; mt < 2; mt++)
#pragma unroll
                for (int ng = 0; ng < 2; ng++)
#pragma unroll
                    for (int sn = 0; sn < 2; sn++) {
                        unsigned bh2[2] = {bhf[ng][sn], bhf[ng][sn + 2]};
                        unsigned bl2[2] = {blf[ng][sn], blf[ng][sn + 2]};
                        float* a = acc[mt][ng * 2 + sn];
                        mma_f16(a, ahf[mt], bh2);
                        mma_f16(a, ahf[mt], bl2);
                        mma_f16(a, alf[mt], bh2);
                    }
        }

        if (more) {
            char* st = smem + ((kt + 1) & 1) * STAGE_B;
            *reinterpret_cast<uint4*>(st + 0 * TILE_B + sts_off) = vah;
            *reinterpret_cast<uint4*>(st + 1 * TILE_B + sts_off) = val;
            *reinterpret_cast<uint4*>(st + 2 * TILE_B + sts_off) = vbh;
            *reinterpret_cast<uint4*>(st + 3 * TILE_B + sts_off) = vbl;
        }
        __syncthreads();
    }

    // ---- Epilogue ----
#pragma unroll
    for (int mt = 0; mt < 2; mt++)
#pragma unroll
        for (int ng = 0; ng < 2; ng++)
#pragma unroll
            for (int sn = 0; sn < 2; sn++) {
                int c = colBase + wc * 32 + ng * 16 + sn * 8 + 2 * tig;
                int r0 = rowBase + wr * 32 + mt * 16 + gid;
                int r1 = r0 + 8;
                float* a = acc[mt][ng * 2 + sn];
                if (MODE == 1) {
                    if (c < H2DIM) {
                        float s0 = __ldg(&gml[c]) * rsqrtf(__ldg(&vrl[c]) + 1e-5f);
                        float t0 = (__ldg(&bias[c]) - __ldg(&mnl[c])) * s0 + __ldg(&btl[c]);
                        float s1 = __ldg(&gml[c + 1]) * rsqrtf(__ldg(&vrl[c + 1]) + 1e-5f);
                        float t1 = (__ldg(&bias[c + 1]) - __ldg(&mnl[c + 1])) * s1 + __ldg(&btl[c + 1]);
                        if (r0 < NNODES) {
                            float v0 = fmaxf(fmaf(a[0], s0, t0), 0.f);
                            float v1 = fmaxf(fmaf(a[1], s1, t1), 0.f);
                            __half h00, h01, h10, h11;
                            split2(v0, h00, h10);
                            split2(v1, h01, h11);
                            *reinterpret_cast<__half2*>(g_t0 + (size_t)r0 * KP2 + c) =
                                __halves2half2(h00, h01);
                            *reinterpret_cast<__half2*>(g_t1 + (size_t)r0 * KP2 + c) =
                                __halves2half2(h10, h11);
                        }
                        if (r1 < NNODES) {
                            float v0 = fmaxf(fmaf(a[2], s0, t0), 0.f);
                            float v1 = fmaxf(fmaf(a[3], s1, t1), 0.f);
                            __half h00, h01, h10, h11;
                            split2(v0, h00, h10);
                            split2(v1, h01, h11);
                            *reinterpret_cast<__half2*>(g_t0 + (size_t)r1 * KP2 + c) =
                                __halves2half2(h00, h01);
                            *reinterpret_cast<__half2*>(g_t1 + (size_t)r1 * KP2 + c) =
                                __halves2half2(h10, h11);
                        }
                    } else if (c < KP2) {
                        __half2 z = __halves2half2(__ushort_as_half(0), __ushort_as_half(0));
                        if (r0 < NNODES) {
                            *reinterpret_cast<__half2*>(g_t0 + (size_t)r0 * KP2 + c) = z;
                            *reinterpret_cast<__half2*>(g_t1 + (size_t)r0 * KP2 + c) = z;
                        }
                        if (r1 < NNODES) {
                            *reinterpret_cast<__half2*>(g_t0 + (size_t)r1 * KP2 + c) = z;
                            *reinterpret_cast<__half2*>(g_t1 + (size_t)r1 * KP2 + c) = z;
                        }
                    }
                } else {
                    if (c < HDIM) {
                        float t0 = __ldg(&bias[c]);
                        float t1 = __ldg(&bias[c + 1]);
                        if (r0 < NNODES) {
                            float2 o = make_float2(a[0] + t0, a[1] + t1);
                            *reinterpret_cast<float2*>(g_h + (size_t)r0 * HDIM + c) = o;
                        }
                        if (r1 < NNODES) {
                            float2 o = make_float2(a[2] + t0, a[3] + t1);
                            *reinterpret_cast<float2*>(g_h + (size_t)r1 * HDIM + c) = o;
                        }
                    }
                }
            }
}

// ---------------- Pooling scatter ----------------
__global__ void pool_kernel(const int* __restrict__ batch) {
    int n = blockIdx.x * 8 + (threadIdx.x >> 5);
    if (n >= NNODES) return;
    int lane = threadIdx.x & 31;
    int g = __ldg(&batch[n]);
    const float4* hr = reinterpret_cast<const float4*>(g_h + (size_t)n * HDIM);
    float* gs = g_gsum + (size_t)g * HDIM;
#pragma unroll 3
    for (int c = lane; c < HDIM / 4; c += 32)
        red_add_v4(gs + 4 * c, hr[c]);
    if (lane == 0) atomicAdd(&g_gcnt[g], 1.0f);
}

// ---------------- Final: graph_feature + logits ----------------
__global__ void final_kernel(const float* __restrict__ cls_W, const float* __restrict__ cls_b,
                             float* __restrict__ out, int write_gf) {
    int g = blockIdx.x;
    int tid = threadIdx.x;
    float inv = 1.0f / fmaxf(g_gcnt[g], 1.0f);
    float d0 = 0.f, d1 = 0.f;
    for (int j = tid; j < HDIM; j += blockDim.x) {
        float gf = g_gsum[(size_t)g * HDIM + j] * inv;
        if (write_gf) out[2 * NGRAPHS + (size_t)g * HDIM + j] = gf;
        d0 += gf * __ldg(&cls_W[j * 2 + 0]);
        d1 += gf * __ldg(&cls_W[j * 2 + 1]);
    }
    __shared__ float s0[128], s1[128];
    s0[tid] = d0;
    s1[tid] = d1;
    __syncthreads();
    for (int o = 64; o > 0; o >>= 1) {
        if (tid < o) { s0[tid] += s0[tid + o]; s1[tid] += s1[tid + o]; }
        __syncthreads();
    }
    if (tid == 0) {
        out[g * 2 + 0] = s0[0] + __ldg(&cls_b[0]);
        out[g * 2 + 1] = s1[0] + __ldg(&cls_b[1]);
    }
}

// ---------------- Launcher ----------------
extern "C" void kernel_launch(void* const* d_in, const int* in_sizes, int n_in,
                              void* d_out, int out_size) {
    const int* x          = (const int*)d_in[0];
    const int* edge_index = (const int*)d_in[1];
    const int* edge_attr  = (const int*)d_in[2];
    const int* batch      = (const int*)d_in[3];
    const float* atom_emb = (const float*)d_in[4];
    const float* bond_emb = (const float*)d_in[5];
    const float* eps      = (const float*)d_in[6];
    const float* W1       = (const float*)d_in[7];
    const float* b1       = (const float*)d_in[8];
    const float* bn_gamma = (const float*)d_in[9];
    const float* bn_beta  = (const float*)d_in[10];
    const float* bn_mean  = (const float*)d_in[11];
    const float* bn_var   = (const float*)d_in[12];
    const float* W2       = (const float*)d_in[13];
    const float* b2       = (const float*)d_in[14];
    const float* cls_W    = (const float*)d_in[15];
    const float* cls_b    = (const float*)d_in[16];
    float* out = (float*)d_out;

    cudaFuncSetAttribute(gemm_f16_kernel<1>, cudaFuncAttributeMaxDynamicSharedMemorySize, GSMEM);
    cudaFuncSetAttribute(gemm_f16_kernel<2>, cudaFuncAttributeMaxDynamicSharedMemorySize, GSMEM);

    atom_kernel<<<NNODES, 128>>>(x, atom_emb);
    zero_pool_kernel<<<1184, 256>>>();
    prepack_w_kernel<<<(W1P_TOTAL + W2P_TOTAL + 255) / 256, 256>>>(W1, W2);

    dim3 g1grid(5, (NNODES + 127) / 128);
    dim3 g2grid(3, (NNODES + 127) / 128);

    for (int l = 0; l < NLAYERS; l++) {
        zero_agg_kernel<<<4096, 256>>>();
        edge_kernel<<<(NEDGES + 7) / 8, 256>>>(edge_index, edge_attr,
                                               bond_emb + (size_t)l * 3 * 16 * HDIM);
        prepack_a_kernel<<<(NNODES * 80 + 255) / 256, 256>>>(eps + l);
        gemm_f16_kernel<1><<<g1grid, 512, GSMEM>>>(
            l, b1 + (size_t)l * H2DIM,
            bn_gamma + (size_t)l * H2DIM, bn_beta + (size_t)l * H2DIM,
            bn_mean + (size_t)l * H2DIM, bn_var + (size_t)l * H2DIM);
        gemm_f16_kernel<2><<<g2grid, 512, GSMEM>>>(
            l, b2 + (size_t)l * HDIM, nullptr, nullptr, nullptr, nullptr);
    }

    pool_kernel<<<(NNODES + 7) / 8, 256>>>(batch);
    int write_gf = (out_size >= 2 * NGRAPHS + NGRAPHS * HDIM) ? 1 : 0;
    final_kernel<<<NGRAPHS, 128>>>(cls_W, cls_b, out, write_gf);
}

// round 14
// speedup vs baseline: 2.3319x; 1.5105x over previous
#include <cuda_runtime.h>
#include <cuda_fp16.h>
#include <cstdint>
#include <cstddef>

// ---------------- Problem constants ----------------
#define NNODES 200000
#define NEDGES 400000
#define NGRAPHS 4096
#define HDIM 300
#define H2DIM 600
#define NLAYERS 5
#define KP1 320   // padded K for gemm1 operands (>=300, mult of 32)
#define KP2 608   // padded K for gemm2 operands (>=600, mult of 32)

// ---------------- Scratch (device globals; no allocation allowed) ----------------
__device__ float g_h[(size_t)NNODES * HDIM];      // node features (fp32)
__device__ float g_agg[(size_t)NNODES * HDIM];    // scatter-add accumulator
__device__ __half g_a0[(size_t)NNODES * KP1];     // gemm1 A hi-split
__device__ __half g_a1[(size_t)NNODES * KP1];     // gemm1 A lo-split
__device__ __half g_t0[(size_t)NNODES * KP2];     // gemm1 out / gemm2 A hi-split
__device__ __half g_t1[(size_t)NNODES * KP2];     // lo-split
__device__ __half g_w1p0[(size_t)NLAYERS * H2DIM * KP1];  // W1 transposed+split [l][n][k]
__device__ __half g_w1p1[(size_t)NLAYERS * H2DIM * KP1];
__device__ __half g_w2p0[(size_t)NLAYERS * HDIM * KP2];   // W2 transposed+split
__device__ __half g_w2p1[(size_t)NLAYERS * HDIM * KP2];
__device__ float g_gsum[(size_t)NGRAPHS * HDIM];
__device__ float g_gcnt[NGRAPHS];

// ---------------- PTX helpers ----------------
__device__ __forceinline__ void red_add_v4(float* p, float4 v) {
    asm volatile("red.global.add.v4.f32 [%0], {%1, %2, %3, %4};"
                 :: "l"(p), "f"(v.x), "f"(v.y), "f"(v.z), "f"(v.w) : "memory");
}
__device__ __forceinline__ uint32_t smem_u32(const void* p) {
    uint32_t a;
    asm("{ .reg .u64 t; cvta.to.shared.u64 t, %1; cvt.u32.u64 %0, t; }" : "=r"(a) : "l"(p));
    return a;
}
__device__ __forceinline__ void mma_f16(float* d, const unsigned* a, const unsigned* b) {
    asm volatile(
        "mma.sync.aligned.m16n8k16.row.col.f32.f16.f16.f32 "
        "{%0,%1,%2,%3}, {%4,%5,%6,%7}, {%8,%9}, {%0,%1,%2,%3};"
        : "+f"(d[0]), "+f"(d[1]), "+f"(d[2]), "+f"(d[3])
        : "r"(a[0]), "r"(a[1]), "r"(a[2]), "r"(a[3]), "r"(b[0]), "r"(b[1]));
}
__device__ __forceinline__ void ldm_x4(unsigned* r, uint32_t addr) {
    asm volatile("ldmatrix.sync.aligned.m8n8.x4.shared.b16 {%0,%1,%2,%3}, [%4];"
                 : "=r"(r[0]), "=r"(r[1]), "=r"(r[2]), "=r"(r[3]) : "r"(addr));
}
__device__ __forceinline__ void split2(float v, __half& h0, __half& h1) {
    h0 = __float2half_rn(v);
    h1 = __float2half_rn(v - __half2float(h0));
}
// cp.async 16B with zero-fill when !pred (src-size=0)
__device__ __forceinline__ void cp_async16(uint32_t dst, const void* src, bool pred) {
    int sz = pred ? 16 : 0;
    asm volatile("cp.async.ca.shared.global [%0], [%1], 16, %2;"
                 :: "r"(dst), "l"(src), "r"(sz) : "memory");
}
__device__ __forceinline__ void cp_commit() {
    asm volatile("cp.async.commit_group;" ::: "memory");
}
template <int N>
__device__ __forceinline__ void cp_wait() {
    asm volatile("cp.async.wait_group %0;" :: "n"(N) : "memory");
}

// ---------------- Zeroing kernels ----------------
__global__ void zero_agg_kernel() {
    float4* p = reinterpret_cast<float4*>(g_agg);
    int n4 = (NNODES * HDIM) / 4;
    for (int i = blockIdx.x * blockDim.x + threadIdx.x; i < n4; i += gridDim.x * blockDim.x)
        p[i] = make_float4(0.f, 0.f, 0.f, 0.f);
}
__global__ void zero_pool_kernel() {
    float4* p = reinterpret_cast<float4*>(g_gsum);
    int n4 = (NGRAPHS * HDIM) / 4;
    for (int i = blockIdx.x * blockDim.x + threadIdx.x; i < n4; i += gridDim.x * blockDim.x)
        p[i] = make_float4(0.f, 0.f, 0.f, 0.f);
    for (int i = blockIdx.x * blockDim.x + threadIdx.x; i < NGRAPHS; i += gridDim.x * blockDim.x)
        g_gcnt[i] = 0.f;
}

// ---------------- Weight prepack: transpose + fp16 split, all layers ----------------
#define W1P_TOTAL (NLAYERS * H2DIM * KP1)
#define W2P_TOTAL (NLAYERS * HDIM * KP2)
__global__ void prepack_w_kernel(const float* __restrict__ W1, const float* __restrict__ W2) {
    int idx = blockIdx.x * blockDim.x + threadIdx.x;
    if (idx < W1P_TOTAL) {
        int l = idx / (H2DIM * KP1);
        int rem = idx % (H2DIM * KP1);
        int n = rem / KP1, k = rem % KP1;
        float v = (k < HDIM) ? __ldg(&W1[((size_t)l * HDIM + k) * H2DIM + n]) : 0.f;
        __half h0, h1;
        split2(v, h0, h1);
        g_w1p0[idx] = h0;
        g_w1p1[idx] = h1;
    } else if (idx < W1P_TOTAL + W2P_TOTAL) {
        int j = idx - W1P_TOTAL;
        int l = j / (HDIM * KP2);
        int rem = j % (HDIM * KP2);
        int n = rem / KP2, k = rem % KP2;
        float v = (k < H2DIM) ? __ldg(&W2[((size_t)l * H2DIM + k) * HDIM + n]) : 0.f;
        __half h0, h1;
        split2(v, h0, h1);
        g_w2p0[j] = h0;
        g_w2p1[j] = h1;
    }
}

// ---------------- A prepack for gemm1: v=(1+eps)h+agg, split -> g_a0/g_a1 ----------------
__global__ void prepack_a_kernel(const float* __restrict__ epsp) {
    int idx = blockIdx.x * blockDim.x + threadIdx.x;  // row * 80 + g4
    if (idx >= NNODES * 80) return;
    int row = idx / 80, g4 = idx % 80;
    __half2 z0[2], z1[2];
    if (g4 < 75) {
        float epv = 1.0f + __ldg(epsp);
        float4 hv = *reinterpret_cast<const float4*>(g_h + (size_t)row * HDIM + g4 * 4);
        float4 gv = *reinterpret_cast<const float4*>(g_agg + (size_t)row * HDIM + g4 * 4);
        float v[4] = {fmaf(epv, hv.x, gv.x), fmaf(epv, hv.y, gv.y),
                      fmaf(epv, hv.z, gv.z), fmaf(epv, hv.w, gv.w)};
        __half h0[4], h1[4];
#pragma unroll
        for (int j = 0; j < 4; j++) split2(v[j], h0[j], h1[j]);
        z0[0] = __halves2half2(h0[0], h0[1]);
        z0[1] = __halves2half2(h0[2], h0[3]);
        z1[0] = __halves2half2(h1[0], h1[1]);
        z1[1] = __halves2half2(h1[2], h1[3]);
    } else {
        z0[0] = z0[1] = z1[0] = z1[1] = __halves2half2(__ushort_as_half(0), __ushort_as_half(0));
    }
    *reinterpret_cast<__half2*>(g_a0 + (size_t)row * KP1 + g4 * 4) = z0[0];
    *reinterpret_cast<__half2*>(g_a0 + (size_t)row * KP1 + g4 * 4 + 2) = z0[1];
    *reinterpret_cast<__half2*>(g_a1 + (size_t)row * KP1 + g4 * 4) = z1[0];
    *reinterpret_cast<__half2*>(g_a1 + (size_t)row * KP1 + g4 * 4 + 2) = z1[1];
}

// ---------------- Atom encoder ----------------
__global__ void atom_kernel(const int* __restrict__ x, const float* __restrict__ atom_emb) {
    int n = blockIdx.x;
    __shared__ int sx[9];
    if (threadIdx.x < 9) sx[threadIdx.x] = x[n * 9 + threadIdx.x];
    __syncthreads();
    for (int j = threadIdx.x; j < HDIM; j += blockDim.x) {
        float s = 0.f;
#pragma unroll
        for (int f = 0; f < 9; f++)
            s += __ldg(&atom_emb[((size_t)(f * 120 + sx[f])) * HDIM + j]);
        g_h[(size_t)n * HDIM + j] = s;
    }
}

// ---------------- Edge kernel: agg[dst] += relu(h[src] + e) ----------------
__global__ void edge_kernel(const int* __restrict__ edge_index,
                            const int* __restrict__ edge_attr,
                            const float* __restrict__ bond_l) {
    int e = blockIdx.x * 8 + (threadIdx.x >> 5);
    if (e >= NEDGES) return;
    int lane = threadIdx.x & 31;
    int src = __ldg(&edge_index[e]);
    int dst = __ldg(&edge_index[NEDGES + e]);
    int a0 = __ldg(&edge_attr[e * 3 + 0]);
    int a1 = __ldg(&edge_attr[e * 3 + 1]);
    int a2 = __ldg(&edge_attr[e * 3 + 2]);
    const float4* b0 = reinterpret_cast<const float4*>(bond_l + (size_t)(0 * 16 + a0) * HDIM);
    const float4* b1 = reinterpret_cast<const float4*>(bond_l + (size_t)(1 * 16 + a1) * HDIM);
    const float4* b2 = reinterpret_cast<const float4*>(bond_l + (size_t)(2 * 16 + a2) * HDIM);
    const float4* hs = reinterpret_cast<const float4*>(g_h + (size_t)src * HDIM);
    float* ag = g_agg + (size_t)dst * HDIM;
#pragma unroll 3
    for (int c = lane; c < HDIM / 4; c += 32) {
        float4 e0 = __ldg(&b0[c]);
        float4 e1 = __ldg(&b1[c]);
        float4 e2 = __ldg(&b2[c]);
        float4 hv = hs[c];
        float4 m;
        m.x = fmaxf(hv.x + e0.x + e1.x + e2.x, 0.f);
        m.y = fmaxf(hv.y + e0.y + e1.y + e2.y, 0.f);
        m.z = fmaxf(hv.z + e0.z + e1.z + e2.z, 0.f);
        m.w = fmaxf(hv.w + e0.w + e1.w + e2.w, 0.f);
        red_add_v4(ag + 4 * c, m);
    }
}

// ---------------- Tensor-core GEMM (prepacked 3xFP16 split, cp.async pipeline) ----------------
// 512 threads (16 warps, 4x4), block tile 128x128, warp tile 32x32, K-chunk 32.
// 3-stage cp.async ring; stages of 4 tiles (Ah, Al, Bh, Bl), each 128x32 half (8KB),
// XOR-swizzled 16B chunks (conflict-free STS + ldmatrix).
// acc += Ah*Bh + Ah*Bl + Al*Bh.
#define TILE_B 8192
#define STAGE_B (4 * TILE_B)
#define NSTAGE 3
#define GSMEM (NSTAGE * STAGE_B)

template <int MODE>
__global__ __launch_bounds__(512) void gemm_f16_kernel(
    int l,
    const float* __restrict__ bias,
    const float* __restrict__ gml, const float* __restrict__ btl,
    const float* __restrict__ mnl, const float* __restrict__ vrl) {
    constexpr int KP = (MODE == 1) ? KP1 : KP2;
    constexpr int NC = (MODE == 1) ? H2DIM : HDIM;
    constexpr int NKT = KP / 32;

    extern __shared__ __align__(128) char smem[];
    const uint32_t sb = smem_u32(smem);

    const __half* Ah = (MODE == 1) ? g_a0 : g_t0;
    const __half* Al = (MODE == 1) ? g_a1 : g_t1;
    const __half* Bh = (MODE == 1) ? (g_w1p0 + (size_t)l * H2DIM * KP1)
                                   : (g_w2p0 + (size_t)l * HDIM * KP2);
    const __half* Bl = (MODE == 1) ? (g_w1p1 + (size_t)l * H2DIM * KP1)
                                   : (g_w2p1 + (size_t)l * HDIM * KP2);

    int tid = threadIdx.x;
    int lane = tid & 31, w = tid >> 5;
    int wr = w & 3, wc = w >> 2;
    int gid = lane >> 2, tig = lane & 3;
    int ml = lane & 15, khalf = lane >> 4;
    int rowBase = blockIdx.y * 128, colBase = blockIdx.x * 128;

    // cp.async mapping: thread -> (lrow, w4); each kt advances 64 bytes along K
    int lrow = tid >> 2, w4 = tid & 3;
    int garow = rowBase + lrow;
    int gbrow = colBase + lrow;
    bool aok = (garow < NNODES);
    bool bok = (gbrow < NC);
    int sa_row = aok ? garow : 0;  // safe address base even when predicated off
    int sb_row = bok ? gbrow : 0;
    const char* pAh = reinterpret_cast<const char*>(Ah + (size_t)sa_row * KP + w4 * 8);
    const char* pAl = reinterpret_cast<const char*>(Al + (size_t)sa_row * KP + w4 * 8);
    const char* pBh = reinterpret_cast<const char*>(Bh + (size_t)sb_row * KP + w4 * 8);
    const char* pBl = reinterpret_cast<const char*>(Bl + (size_t)sb_row * KP + w4 * 8);
    uint32_t sts_off = (uint32_t)lrow * 64 + (uint32_t)((w4 ^ ((lrow >> 1) & 3)) * 16);

    float acc[2][4][4];
#pragma unroll
    for (int mt = 0; mt < 2; mt++)
#pragma unroll
        for (int nt = 0; nt < 4; nt++)
#pragma unroll
            for (int i = 0; i < 4; i++) acc[mt][nt][i] = 0.f;

    auto issue_stage = [&](int kt) {
        uint32_t st = sb + (uint32_t)(kt % NSTAGE) * STAGE_B + sts_off;
        size_t go = (size_t)kt * 64;
        cp_async16(st + 0 * TILE_B, pAh + go, aok);
        cp_async16(st + 1 * TILE_B, pAl + go, aok);
        cp_async16(st + 2 * TILE_B, pBh + go, bok);
        cp_async16(st + 3 * TILE_B, pBl + go, bok);
    };

    issue_stage(0);
    cp_commit();
    issue_stage(1);
    cp_commit();

    for (int kt = 0; kt < NKT; kt++) {
        if (kt + 2 < NKT) issue_stage(kt + 2);
        cp_commit();
        cp_wait<2>();
        __syncthreads();

        uint32_t stg = sb + (uint32_t)(kt % NSTAGE) * STAGE_B;
#pragma unroll
        for (int kc = 0; kc < 2; kc++) {
            unsigned ahf[2][4], alf[2][4], bhf[2][4], blf[2][4];
#pragma unroll
            for (int mt = 0; mt < 2; mt++) {
                int r = wr * 32 + mt * 16 + ml;
                uint32_t off = (uint32_t)r * 64 +
                               (uint32_t)(((kc * 2 + khalf) ^ ((r >> 1) & 3)) * 16);
                ldm_x4(ahf[mt], stg + 0 * TILE_B + off);
                ldm_x4(alf[mt], stg + 1 * TILE_B + off);
            }
#pragma unroll
            for (int ng = 0; ng < 2; ng++) {
                int r = wc * 32 + ng * 16 + ml;
                uint32_t off = (uint32_t)r * 64 +
                               (uint32_t)(((kc * 2 + khalf) ^ ((r >> 1) & 3)) * 16);
                ldm_x4(bhf[ng], stg + 2 * TILE_B + off);
                ldm_x4(blf[ng], stg + 3 * TILE_B + off);
            }
#pragma unroll
            for (int mt = 0; mt < 2; mt++)
#pragma unroll
                for (int ng = 0; ng < 2; ng++)
#pragma unroll
                    for (int sn = 0; sn < 2; sn++) {
                        unsigned bh2[2] = {bhf[ng][sn], bhf[ng][sn + 2]};
                        unsigned bl2[2] = {blf[ng][sn], blf[ng][sn + 2]};
                        float* a = acc[mt][ng * 2 + sn];
                        mma_f16(a, ahf[mt], bh2);
                        mma_f16(a, ahf[mt], bl2);
                        mma_f16(a, alf[mt], bh2);
                    }
        }
        __syncthreads();
    }

    // ---- Epilogue ----
#pragma unroll
    for (int mt = 0; mt < 2; mt++)
#pragma unroll
        for (int ng = 0; ng < 2; ng++)
#pragma unroll
            for (int sn = 0; sn < 2; sn++) {
                int c = colBase + wc * 32 + ng * 16 + sn * 8 + 2 * tig;
                int r0 = rowBase + wr * 32 + mt * 16 + gid;
                int r1 = r0 + 8;
                float* a = acc[mt][ng * 2 + sn];
                if (MODE == 1) {
                    if (c < H2DIM) {
                        float s0 = __ldg(&gml[c]) * rsqrtf(__ldg(&vrl[c]) + 1e-5f);
                        float t0 = (__ldg(&bias[c]) - __ldg(&mnl[c])) * s0 + __ldg(&btl[c]);
                        float s1 = __ldg(&gml[c + 1]) * rsqrtf(__ldg(&vrl[c + 1]) + 1e-5f);
                        float t1 = (__ldg(&bias[c + 1]) - __ldg(&mnl[c + 1])) * s1 + __ldg(&btl[c + 1]);
                        if (r0 < NNODES) {
                            float v0 = fmaxf(fmaf(a[0], s0, t0), 0.f);
                            float v1 = fmaxf(fmaf(a[1], s1, t1), 0.f);
                            __half h00, h01, h10, h11;
                            split2(v0, h00, h10);
                            split2(v1, h01, h11);
                            *reinterpret_cast<__half2*>(g_t0 + (size_t)r0 * KP2 + c) =
                                __halves2half2(h00, h01);
                            *reinterpret_cast<__half2*>(g_t1 + (size_t)r0 * KP2 + c) =
                                __halves2half2(h10, h11);
                        }
                        if (r1 < NNODES) {
                            float v0 = fmaxf(fmaf(a[2], s0, t0), 0.f);
                            float v1 = fmaxf(fmaf(a[3], s1, t1), 0.f);
                            __half h00, h01, h10, h11;
                            split2(v0, h00, h10);
                            split2(v1, h01, h11);
                            *reinterpret_cast<__half2*>(g_t0 + (size_t)r1 * KP2 + c) =
                                __halves2half2(h00, h01);
                            *reinterpret_cast<__half2*>(g_t1 + (size_t)r1 * KP2 + c) =
                                __halves2half2(h10, h11);
                        }
                    } else if (c < KP2) {
                        __half2 z = __halves2half2(__ushort_as_half(0), __ushort_as_half(0));
                        if (r0 < NNODES) {
                            *reinterpret_cast<__half2*>(g_t0 + (size_t)r0 * KP2 + c) = z;
                            *reinterpret_cast<__half2*>(g_t1 + (size_t)r0 * KP2 + c) = z;
                        }
                        if (r1 < NNODES) {
                            *reinterpret_cast<__half2*>(g_t0 + (size_t)r1 * KP2 + c) = z;
                            *reinterpret_cast<__half2*>(g_t1 + (size_t)r1 * KP2 + c) = z;
                        }
                    }
                } else {
                    if (c < HDIM) {
                        float t0 = __ldg(&bias[c]);
                        float t1 = __ldg(&bias[c + 1]);
                        if (r0 < NNODES) {
                            float2 o = make_float2(a[0] + t0, a[1] + t1);
                            *reinterpret_cast<float2*>(g_h + (size_t)r0 * HDIM + c) = o;
                        }
                        if (r1 < NNODES) {
                            float2 o = make_float2(a[2] + t0, a[3] + t1);
                            *reinterpret_cast<float2*>(g_h + (size_t)r1 * HDIM + c) = o;
                        }
                    }
                }
            }
}

// ---------------- Pooling scatter ----------------
__global__ void pool_kernel(const int* __restrict__ batch) {
    int n = blockIdx.x * 8 + (threadIdx.x >> 5);
    if (n >= NNODES) return;
    int lane = threadIdx.x & 31;
    int g = __ldg(&batch[n]);
    const float4* hr = reinterpret_cast<const float4*>(g_h + (size_t)n * HDIM);
    float* gs = g_gsum + (size_t)g * HDIM;
#pragma unroll 3
    for (int c = lane; c < HDIM / 4; c += 32)
        red_add_v4(gs + 4 * c, hr[c]);
    if (lane == 0) atomicAdd(&g_gcnt[g], 1.0f);
}

// ---------------- Final: graph_feature + logits ----------------
__global__ void final_kernel(const float* __restrict__ cls_W, const float* __restrict__ cls_b,
                             float* __restrict__ out, int write_gf) {
    int g = blockIdx.x;
    int tid = threadIdx.x;
    float inv = 1.0f / fmaxf(g_gcnt[g], 1.0f);
    float d0 = 0.f, d1 = 0.f;
    for (int j = tid; j < HDIM; j += blockDim.x) {
        float gf = g_gsum[(size_t)g * HDIM + j] * inv;
        if (write_gf) out[2 * NGRAPHS + (size_t)g * HDIM + j] = gf;
        d0 += gf * __ldg(&cls_W[j * 2 + 0]);
        d1 += gf * __ldg(&cls_W[j * 2 + 1]);
    }
    __shared__ float s0[128], s1[128];
    s0[tid] = d0;
    s1[tid] = d1;
    __syncthreads();
    for (int o = 64; o > 0; o >>= 1) {
        if (tid < o) { s0[tid] += s0[tid + o]; s1[tid] += s1[tid + o]; }
        __syncthreads();
    }
    if (tid == 0) {
        out[g * 2 + 0] = s0[0] + __ldg(&cls_b[0]);
        out[g * 2 + 1] = s1[0] + __ldg(&cls_b[1]);
    }
}

// ---------------- Launcher ----------------
extern "C" void kernel_launch(void* const* d_in, const int* in_sizes, int n_in,
                              void* d_out, int out_size) {
    const int* x          = (const int*)d_in[0];
    const int* edge_index = (const int*)d_in[1];
    const int* edge_attr  = (const int*)d_in[2];
    const int* batch      = (const int*)d_in[3];
    const float* atom_emb = (const float*)d_in[4];
    const float* bond_emb = (const float*)d_in[5];
    const float* eps      = (const float*)d_in[6];
    const float* W1       = (const float*)d_in[7];
    const float* b1       = (const float*)d_in[8];
    const float* bn_gamma = (const float*)d_in[9];
    const float* bn_beta  = (const float*)d_in[10];
    const float* bn_mean  = (const float*)d_in[11];
    const float* bn_var   = (const float*)d_in[12];
    const float* W2       = (const float*)d_in[13];
    const float* b2       = (const float*)d_in[14];
    const float* cls_W    = (const float*)d_in[15];
    const float* cls_b    = (const float*)d_in[16];
    float* out = (float*)d_out;

    cudaFuncSetAttribute(gemm_f16_kernel<1>, cudaFuncAttributeMaxDynamicSharedMemorySize, GSMEM);
    cudaFuncSetAttribute(gemm_f16_kernel<2>, cudaFuncAttributeMaxDynamicSharedMemorySize, GSMEM);

    atom_kernel<<<NNODES, 128>>>(x, atom_emb);
    zero_pool_kernel<<<1184, 256>>>();
    prepack_w_kernel<<<(W1P_TOTAL + W2P_TOTAL + 255) / 256, 256>>>(W1, W2);

    dim3 g1grid(5, (NNODES + 127) / 128);
    dim3 g2grid(3, (NNODES + 127) / 128);

    for (int l = 0; l < NLAYERS; l++) {
        zero_agg_kernel<<<4096, 256>>>();
        edge_kernel<<<(NEDGES + 7) / 8, 256>>>(edge_index, edge_attr,
                                               bond_emb + (size_t)l * 3 * 16 * HDIM);
        prepack_a_kernel<<<(NNODES * 80 + 255) / 256, 256>>>(eps + l);
        gemm_f16_kernel<1><<<g1grid, 512, GSMEM>>>(
            l, b1 + (size_t)l * H2DIM,
            bn_gamma + (size_t)l * H2DIM, bn_beta + (size_t)l * H2DIM,
            bn_mean + (size_t)l * H2DIM, bn_var + (size_t)l * H2DIM);
        gemm_f16_kernel<2><<<g2grid, 512, GSMEM>>>(
            l, b2 + (size_t)l * HDIM, nullptr, nullptr, nullptr, nullptr);
    }

    pool_kernel<<<(NNODES + 7) / 8, 256>>>(batch);
    int write_gf = (out_size >= 2 * NGRAPHS + NGRAPHS * HDIM) ? 1 : 0;
    final_kernel<<<NGRAPHS, 128>>>(cls_W, cls_b, out, write_gf);
}